// round 1
// baseline (speedup 1.0000x reference)
#include <cuda_runtime.h>
#include <cstdint>

#define N_NODES 50000
#define N_EDGES 800000
#define D 128
#define BN_EPS 1e-5f

// ---------------- scratch (no allocations allowed) ----------------
__device__ double g_sum[D];
__device__ double g_sumsq[D];
__device__ float  g_scale[D];   // gamma * rstd
__device__ float  g_bias[D];    // beta - mu * gamma * rstd

// ---------------- K1: zero accumulator + stats ----------------
__global__ void k_zero(float* __restrict__ out) {
    int i = blockIdx.x * blockDim.x + threadIdx.x;
    if (i < D) { g_sum[i] = 0.0; g_sumsq[i] = 0.0; }
    if (i < (N_NODES * D) / 4) {
        ((float4*)out)[i] = make_float4(0.f, 0.f, 0.f, 0.f);
    }
}

// ---------------- K2: edge scatter (warp per edge) ----------------
// lane l of edge e moves float4 chunk l: gather h[src]*norm[src], red-add into out[dst].
__global__ void __launch_bounds__(256) k_edges(
    const float* __restrict__ h, const float* __restrict__ norm,
    const int* __restrict__ src, const int* __restrict__ dst,
    float* __restrict__ out)
{
    long long t = (long long)blockIdx.x * blockDim.x + threadIdx.x;
    int e    = (int)(t >> 5);
    int lane = (int)(t & 31);
    if (e >= N_EDGES) return;

    int s = src[e];          // warp-uniform
    int d = dst[e];          // warp-uniform
    float ns = norm[s];      // warp-uniform

    const float4 hv = ((const float4*)(h + (size_t)s * D))[lane];
    float4 v = make_float4(hv.x * ns, hv.y * ns, hv.z * ns, hv.w * ns);

    float* p = out + (size_t)d * D + lane * 4;
    asm volatile("red.global.add.v4.f32 [%0], {%1,%2,%3,%4};"
                 :: "l"(p), "f"(v.x), "f"(v.y), "f"(v.z), "f"(v.w)
                 : "memory");
}

// ---------------- K3: combine + per-channel partial stats ----------------
// block = 128 threads (one per channel), processes ROWS_PER_BLOCK rows.
#define ROWS_PER_BLOCK 32
__global__ void __launch_bounds__(128) k_combine(
    const float* __restrict__ h, const float* __restrict__ norm,
    const float* __restrict__ eps_p, float* __restrict__ out)
{
    int c    = threadIdx.x;                 // channel 0..127
    int row0 = blockIdx.x * ROWS_PER_BLOCK;
    float epsv = 1.0f + eps_p[0];

    float lsum = 0.f, lsq = 0.f;
#pragma unroll 4
    for (int r = 0; r < ROWS_PER_BLOCK; r++) {
        int row = row0 + r;
        if (row >= N_NODES) break;
        float nrm = norm[row];              // warp-uniform
        size_t idx = (size_t)row * D + c;
        float v = (epsv * h[idx] * nrm + out[idx]) * nrm;
        out[idx] = v;
        lsum += v;
        lsq  += v * v;
    }
    atomicAdd(&g_sum[c],   (double)lsum);
    atomicAdd(&g_sumsq[c], (double)lsq);
}

// ---------------- K4: finalize BN stats (1 block, 128 threads) ----------------
__global__ void k_stats(const float* __restrict__ gamma,
                        const float* __restrict__ beta)
{
    int c = threadIdx.x;
    if (c >= D) return;
    double mu  = g_sum[c]   / (double)N_NODES;
    double var = g_sumsq[c] / (double)N_NODES - mu * mu;
    double rstd = 1.0 / sqrt(var + (double)BN_EPS);
    float s = gamma[c] * (float)rstd;
    g_scale[c] = s;
    g_bias[c]  = beta[c] - (float)mu * s;
}

// ---------------- K5: BN apply + ReLU ----------------
__global__ void __launch_bounds__(256) k_bn(float* __restrict__ out) {
    int i4 = blockIdx.x * blockDim.x + threadIdx.x;
    if (i4 >= (N_NODES * D) / 4) return;
    int cbase = (i4 * 4) & (D - 1);
    float4 x = ((float4*)out)[i4];
    x.x = fmaxf(fmaf(x.x, g_scale[cbase + 0], g_bias[cbase + 0]), 0.f);
    x.y = fmaxf(fmaf(x.y, g_scale[cbase + 1], g_bias[cbase + 1]), 0.f);
    x.z = fmaxf(fmaf(x.z, g_scale[cbase + 2], g_bias[cbase + 2]), 0.f);
    x.w = fmaxf(fmaf(x.w, g_scale[cbase + 3], g_bias[cbase + 3]), 0.f);
    ((float4*)out)[i4] = x;
}

// ---------------- launch ----------------
extern "C" void kernel_launch(void* const* d_in, const int* in_sizes, int n_in,
                              void* d_out, int out_size)
{
    const float* h     = (const float*)d_in[0];
    const float* norm  = (const float*)d_in[1];
    const float* eps   = (const float*)d_in[2];
    const float* gamma = (const float*)d_in[3];
    const float* beta  = (const float*)d_in[4];
    const int*   src   = (const int*)d_in[5];
    const int*   dst   = (const int*)d_in[6];
    float* out = (float*)d_out;

    (void)in_sizes; (void)n_in; (void)out_size;

    const int total4 = (N_NODES * D) / 4;            // 1.6M float4
    k_zero<<<(total4 + 255) / 256, 256>>>(out);

    const long long ethreads = (long long)N_EDGES * 32;
    k_edges<<<(unsigned)((ethreads + 255) / 256), 256>>>(h, norm, src, dst, out);

    const int cblocks = (N_NODES + ROWS_PER_BLOCK - 1) / ROWS_PER_BLOCK;
    k_combine<<<cblocks, 128>>>(h, norm, eps, out);

    k_stats<<<1, 128>>>(gamma, beta);

    k_bn<<<(total4 + 255) / 256, 256>>>(out);
}